// round 7
// baseline (speedup 1.0000x reference)
#include <cuda_runtime.h>
#include <math.h>

// ---------------------------------------------------------------------------
// MultiStreamCNN: two conv-pool streams on same input, concat, fuse conv,
// global mean, 1x1 det head, sigmoid + 3-box NMS.
// All heavy convs use packed fp32x2 FMA (fma.rn.f32x2) = 2 MAC/lane/instr.
// Odd patch stride (conflict-free stride-2 LDS), LDS.128 weight reads.
// ---------------------------------------------------------------------------

typedef unsigned long long u64;

__device__ __forceinline__ u64 pk2(float lo, float hi) {
    u64 r; asm("mov.b64 %0,{%1,%2};" : "=l"(r) : "f"(lo), "f"(hi)); return r;
}
__device__ __forceinline__ u64 pkdup(float v) {
    u64 r; asm("mov.b64 %0,{%1,%1};" : "=l"(r) : "f"(v)); return r;
}
__device__ __forceinline__ void upk(u64 v, float& lo, float& hi) {
    asm("mov.b64 {%0,%1},%2;" : "=f"(lo), "=f"(hi) : "l"(v));
}
__device__ __forceinline__ void fma2(u64& d, u64 a, u64 b) {
    asm("fma.rn.f32x2 %0,%1,%2,%0;" : "+l"(d) : "l"(a), "l"(b));
}

// Scratch (device globals: no runtime allocation allowed)
// s1: [stream*8+b][32][256][256]  pooled stage-1 activations (both streams)
__device__ float g_s1[16u * 32u * 256u * 256u];
// s2: [b][128][128][128]  pooled stage-2 activations (concat[rgb(64), ir(64)])
__device__ float g_s2[8u * 128u * 128u * 128u];
// partial sums of relu(fuse) per (b, oc, tile): deterministic 2-stage reduction
__device__ float g_part[8 * 128 * 16];

#define PSTR 35  // patch row stride (odd -> conflict-free stride-2 access)

// ---------------------------------------------------------------------------
// Kernel A: conv1(3x3, 3->32) + relu + maxpool2 for BOTH streams.
// grid (8, 32, 8*4): x = x-tile(32 pooled wide), y = y-tile(8 pooled tall),
// z = b*4 + ocg.  ocg 0,1 -> rgb channels [0..32); ocg 2,3 -> ir.
// Thread: one pooled pixel, 16 output channels (8 f32x2 pairs) x 4 conv pos.
// ---------------------------------------------------------------------------
__global__ __launch_bounds__(256, 2) void k_s1(
    const float* __restrict__ x,
    const float* __restrict__ rw, const float* __restrict__ rb,
    const float* __restrict__ iw, const float* __restrict__ ib)
{
    __shared__ float patch[3][18][67];
    __shared__ __align__(16) u64 wp[27][8];
    __shared__ u64 bp[8];

    const int tid = threadIdx.x;
    const int bx = blockIdx.x;            // 0..7
    const int by = blockIdx.y;            // 0..31
    const int bz = blockIdx.z;            // b*4+ocg
    const int b = bz >> 2, ocg = bz & 3;
    const int stream = ocg >> 1;
    const int obase = (ocg & 1) * 16;     // local oc base within this stream's 32
    const float* w  = stream ? iw : rw;
    const float* bb = stream ? ib : rb;

    // Prepack weights as (oc, oc+1) pairs: wp[ic*9+ky*3+kx][pr]
    for (int i = tid; i < 27 * 8; i += 256) {
        int pr = i & 7, k = i >> 3;
        int ic = k / 9, kk = k % 9, ky = kk / 3, kx = kk % 3;
        int o0 = obase + 2 * pr;
        wp[k][pr] = pk2(w[((o0 * 3 + ic) * 3 + ky) * 3 + kx],
                        w[(((o0 + 1) * 3 + ic) * 3 + ky) * 3 + kx]);
    }
    if (tid < 8) bp[tid] = pk2(bb[obase + 2 * tid], bb[obase + 2 * tid + 1]);

    // Load input patch (conv region 64x16 + halo) for all 3 input channels
    const int y0 = 16 * by - 1, x0 = 64 * bx - 1;
    const float* xin = x + (size_t)b * 3 * 512 * 512;
    for (int i = tid; i < 3 * 18 * 66; i += 256) {
        int ic = i / (18 * 66); int r = (i / 66) % 18; int c = i % 66;
        int y = y0 + r, xg = x0 + c;
        float v = 0.f;
        if ((unsigned)y < 512u && (unsigned)xg < 512u)
            v = xin[((size_t)ic * 512 + y) * 512 + xg];
        patch[ic][r][c] = v;
    }
    __syncthreads();

    const int tx = tid & 31, ty = tid >> 5;
    u64 acc[4][8];
#pragma unroll
    for (int p = 0; p < 4; p++)
#pragma unroll
        for (int pr = 0; pr < 8; pr++) acc[p][pr] = bp[pr];

#pragma unroll
    for (int ic = 0; ic < 3; ic++)
#pragma unroll
        for (int ky = 0; ky < 3; ky++)
#pragma unroll
            for (int kx = 0; kx < 3; kx++) {
                const int k = ic * 9 + ky * 3 + kx;
                u64 w8[8];
#pragma unroll
                for (int q = 0; q < 4; q++) {
                    ulonglong2 v2 = *(const ulonglong2*)&wp[k][2 * q];
                    w8[2 * q] = v2.x; w8[2 * q + 1] = v2.y;
                }
#pragma unroll
                for (int dy = 0; dy < 2; dy++)
#pragma unroll
                    for (int dx = 0; dx < 2; dx++) {
                        u64 a = pkdup(patch[ic][2 * ty + dy + ky][2 * tx + dx + kx]);
                        const int p = dy * 2 + dx;
#pragma unroll
                        for (int pr = 0; pr < 8; pr++) fma2(acc[p][pr], a, w8[pr]);
                    }
            }

    // relu(max over 4 positions) == max(relu), write NCHW plane
    const int py = 8 * by + ty, px = 32 * bx + tx;
    float* outp = g_s1 + ((((size_t)(stream * 8 + b)) * 32 + obase) * 256 + py) * 256 + px;
#pragma unroll
    for (int pr = 0; pr < 8; pr++) {
        float l0, h0, l1, h1, l2, h2, l3, h3;
        upk(acc[0][pr], l0, h0); upk(acc[1][pr], l1, h1);
        upk(acc[2][pr], l2, h2); upk(acc[3][pr], l3, h3);
        float vlo = fmaxf(fmaxf(fmaxf(l0, l1), fmaxf(l2, l3)), 0.f);
        float vhi = fmaxf(fmaxf(fmaxf(h0, h1), fmaxf(h2, h3)), 0.f);
        outp[(size_t)(2 * pr) * 65536] = vlo;
        outp[(size_t)(2 * pr + 1) * 65536] = vhi;
    }
}

// ---------------------------------------------------------------------------
// Kernel B: conv2(3x3, 32->64) + relu + maxpool2 per stream.
// grid (64, 4, 16): x = tile (8x8 tiles of 16x16 pooled), y = ocg(16 oc each),
// z = stream*8 + b.  Output written at concat channel s*64 + oc.
// ---------------------------------------------------------------------------
__global__ __launch_bounds__(256, 2) void k_s2(
    const float* __restrict__ rw, const float* __restrict__ rb,
    const float* __restrict__ iw, const float* __restrict__ ib)
{
    __shared__ float patch[34 * PSTR];
    __shared__ __align__(16) u64 wp[288][8];   // [ic*9+kk][pr]
    __shared__ u64 bp[8];

    const int tid = threadIdx.x;
    const int t = blockIdx.x;     // 0..63
    const int tX = t & 7, tY = t >> 3;
    const int ocg = blockIdx.y;   // 0..3
    const int bz = blockIdx.z;    // stream*8+b
    const int s = bz >> 3, b = bz & 7;
    const float* w  = s ? iw : rw;
    const float* bb = s ? ib : rb;
    const int obase = ocg * 16;

    for (int i = tid; i < 288 * 8; i += 256) {
        int pr = i & 7, k = i >> 3;
        int ic = k / 9, kk = k % 9, ky = kk / 3, kx = kk % 3;
        int o0 = obase + 2 * pr;
        wp[k][pr] = pk2(w[((o0 * 32 + ic) * 3 + ky) * 3 + kx],
                        w[(((o0 + 1) * 32 + ic) * 3 + ky) * 3 + kx]);
    }
    if (tid < 8) bp[tid] = pk2(bb[obase + 2 * tid], bb[obase + 2 * tid + 1]);
    __syncthreads();  // bp/wp visible

    const int ttx = tid & 15, tty = tid >> 4;
    u64 acc[4][8];
#pragma unroll
    for (int p = 0; p < 4; p++)
#pragma unroll
        for (int pr = 0; pr < 8; pr++) acc[p][pr] = bp[pr];

    const int y0 = 32 * tY - 1, x0 = 32 * tX - 1;
    const float* plane = g_s1 + (size_t)bz * 32 * 65536;

    for (int ic = 0; ic < 32; ic++) {
        __syncthreads();
        const float* pl = plane + (size_t)ic * 65536;
        for (int i = tid; i < 34 * 34; i += 256) {
            int r = i / 34, c = i % 34;
            int y = y0 + r, xg = x0 + c;
            float v = 0.f;
            if ((unsigned)y < 256u && (unsigned)xg < 256u) v = pl[y * 256 + xg];
            patch[r * PSTR + c] = v;
        }
        __syncthreads();
#pragma unroll
        for (int kk = 0; kk < 9; kk++) {
            const int ky = kk / 3, kx = kk % 3;
            u64 w8[8];
#pragma unroll
            for (int q = 0; q < 4; q++) {
                ulonglong2 v2 = *(const ulonglong2*)&wp[ic * 9 + kk][2 * q];
                w8[2 * q] = v2.x; w8[2 * q + 1] = v2.y;
            }
#pragma unroll
            for (int dy = 0; dy < 2; dy++)
#pragma unroll
                for (int dx = 0; dx < 2; dx++) {
                    u64 a = pkdup(patch[(2 * tty + dy + ky) * PSTR + 2 * ttx + dx + kx]);
                    const int p = dy * 2 + dx;
#pragma unroll
                    for (int pr = 0; pr < 8; pr++) fma2(acc[p][pr], a, w8[pr]);
                }
        }
    }

    const int py = 16 * tY + tty, px = 16 * tX + ttx;
    float* outp = g_s2 + ((size_t)(b * 128 + s * 64 + obase) * 128 + py) * 128 + px;
#pragma unroll
    for (int pr = 0; pr < 8; pr++) {
        float l0, h0, l1, h1, l2, h2, l3, h3;
        upk(acc[0][pr], l0, h0); upk(acc[1][pr], l1, h1);
        upk(acc[2][pr], l2, h2); upk(acc[3][pr], l3, h3);
        float vlo = fmaxf(fmaxf(fmaxf(l0, l1), fmaxf(l2, l3)), 0.f);
        float vhi = fmaxf(fmaxf(fmaxf(h0, h1), fmaxf(h2, h3)), 0.f);
        outp[(size_t)(2 * pr) * 16384] = vlo;
        outp[(size_t)(2 * pr + 1) * 16384] = vhi;
    }
}

// ---------------------------------------------------------------------------
// Kernel C: fuse conv(3x3, 128->128) + relu, reduced directly to per-tile
// channel sums (output never materialized).  grid (16, 8, 8):
// x = tile (4x4 tiles of 32x32 pixels), y = ocg, z = b.
// Thread: 2x2 pixels x 16 oc.  Weights staged in 4 ic-chunks of 32.
// Deterministic reduction: shfl tree -> per-warp smem -> g_part[b][oc][tile].
// ---------------------------------------------------------------------------
__global__ __launch_bounds__(256, 2) void k_fuse(
    const float* __restrict__ fw, const float* __restrict__ fb)
{
    __shared__ float patch[34 * PSTR];
    __shared__ __align__(16) u64 wp[288][8];
    __shared__ u64 bp[8];
    __shared__ float red[8][16];

    const int tid = threadIdx.x;
    const int t = blockIdx.x;   // 0..15
    const int tX = t & 3, tY = t >> 2;
    const int ocg = blockIdx.y; // 0..7
    const int b = blockIdx.z;
    const int obase = ocg * 16;

    if (tid < 8) bp[tid] = pk2(fb[obase + 2 * tid], fb[obase + 2 * tid + 1]);
    __syncthreads();

    const int ttx = tid & 15, tty = tid >> 4;
    u64 acc[4][8];
#pragma unroll
    for (int p = 0; p < 4; p++)
#pragma unroll
        for (int pr = 0; pr < 8; pr++) acc[p][pr] = bp[pr];

    const int y0 = 32 * tY - 1, x0 = 32 * tX - 1;

    for (int ch = 0; ch < 4; ch++) {
        __syncthreads();  // previous chunk done with wp
        for (int i = tid; i < 288 * 8; i += 256) {
            int pr = i & 7, k = i >> 3;
            int icc = k / 9, kk = k % 9, ky = kk / 3, kx = kk % 3;
            int ic = ch * 32 + icc;
            int o0 = obase + 2 * pr;
            wp[k][pr] = pk2(fw[((o0 * 128 + ic) * 3 + ky) * 3 + kx],
                            fw[(((o0 + 1) * 128 + ic) * 3 + ky) * 3 + kx]);
        }
        for (int icc = 0; icc < 32; icc++) {
            __syncthreads();  // patch free; also makes wp visible on icc==0
            const int ic = ch * 32 + icc;
            const float* pl = g_s2 + (size_t)(b * 128 + ic) * 16384;
            for (int i = tid; i < 34 * 34; i += 256) {
                int r = i / 34, c = i % 34;
                int y = y0 + r, xg = x0 + c;
                float v = 0.f;
                if ((unsigned)y < 128u && (unsigned)xg < 128u) v = pl[y * 128 + xg];
                patch[r * PSTR + c] = v;
            }
            __syncthreads();
#pragma unroll
            for (int kk = 0; kk < 9; kk++) {
                const int ky = kk / 3, kx = kk % 3;
                u64 w8[8];
#pragma unroll
                for (int q = 0; q < 4; q++) {
                    ulonglong2 v2 = *(const ulonglong2*)&wp[icc * 9 + kk][2 * q];
                    w8[2 * q] = v2.x; w8[2 * q + 1] = v2.y;
                }
#pragma unroll
                for (int dy = 0; dy < 2; dy++)
#pragma unroll
                    for (int dx = 0; dx < 2; dx++) {
                        u64 a = pkdup(patch[(2 * tty + dy + ky) * PSTR + 2 * ttx + dx + kx]);
                        const int p = dy * 2 + dx;
#pragma unroll
                        for (int pr = 0; pr < 8; pr++) fma2(acc[p][pr], a, w8[pr]);
                    }
            }
        }
    }

    // relu + per-thread sum of the 4 pixels, per output channel
    float sum[16];
#pragma unroll
    for (int pr = 0; pr < 8; pr++) {
        float l0, h0, l1, h1, l2, h2, l3, h3;
        upk(acc[0][pr], l0, h0); upk(acc[1][pr], l1, h1);
        upk(acc[2][pr], l2, h2); upk(acc[3][pr], l3, h3);
        sum[2 * pr]     = fmaxf(l0, 0.f) + fmaxf(l1, 0.f) + fmaxf(l2, 0.f) + fmaxf(l3, 0.f);
        sum[2 * pr + 1] = fmaxf(h0, 0.f) + fmaxf(h1, 0.f) + fmaxf(h2, 0.f) + fmaxf(h3, 0.f);
    }
    const int wid = tid >> 5, lid = tid & 31;
#pragma unroll
    for (int o = 0; o < 16; o++) {
        float v = sum[o];
        v += __shfl_down_sync(0xffffffffu, v, 16);
        v += __shfl_down_sync(0xffffffffu, v, 8);
        v += __shfl_down_sync(0xffffffffu, v, 4);
        v += __shfl_down_sync(0xffffffffu, v, 2);
        v += __shfl_down_sync(0xffffffffu, v, 1);
        if (lid == 0) red[wid][o] = v;
    }
    __syncthreads();
    if (tid < 16) {
        float s = 0.f;
        for (int w8 = 0; w8 < 8; w8++) s += red[w8][tid];
        g_part[(b * 128 + obase + tid) * 16 + t] = s;
    }
}

// ---------------------------------------------------------------------------
// Kernel D: finish.  Mean, det 1x1 conv, sigmoid, exact-replica stable NMS,
// write all 288 outputs: p(144) | boxes(96) | scores(24) | keep(24).
// ---------------------------------------------------------------------------
__global__ void k_det(const float* __restrict__ dw, const float* __restrict__ db,
                      float* __restrict__ out)
{
    __shared__ float favg[1024];
    __shared__ float pp[144];
    const int tid = threadIdx.x;  // 256

    for (int i = tid; i < 1024; i += 256) {
        float s = 0.f;
        const float* pr = g_part + i * 16;
#pragma unroll
        for (int t = 0; t < 16; t++) s += pr[t];
        favg[i] = s * (1.f / 16384.f);
    }
    __syncthreads();

    if (tid < 144) {
        const int b = tid / 18, ch = tid % 18;
        float s = db[ch];
        const float* w = dw + ch * 128;
        const float* f = favg + b * 128;
#pragma unroll 8
        for (int c = 0; c < 128; c++) s = fmaf(w[c], f[c], s);
        pp[tid] = s;
        out[tid] = s;  // p layout flat == b*18 + (a*6+c)
    }
    __syncthreads();

    if (tid < 8) {
        const int b = tid;
        const float* P = pp + b * 18;
        float sc[3]; bool conf[3];
        float bx1[3], by1[3], bx2[3], by2[3];
        for (int a = 0; a < 3; a++) {
            bx1[a] = P[a * 6 + 0]; by1[a] = P[a * 6 + 1];
            bx2[a] = P[a * 6 + 2]; by2[a] = P[a * 6 + 3];
            sc[a] = 1.f / (1.f + expf(-P[a * 6 + 4]));
            conf[a] = sc[a] > 0.5f;
            out[144 + b * 12 + a * 4 + 0] = bx1[a];
            out[144 + b * 12 + a * 4 + 1] = by1[a];
            out[144 + b * 12 + a * 4 + 2] = bx2[a];
            out[144 + b * 12 + a * 4 + 3] = by2[a];
            out[240 + b * 3 + a] = sc[a];
        }
        // stable descending argsort of masked scores (ties by index)
        float m[3];
        for (int a = 0; a < 3; a++) m[a] = conf[a] ? sc[a] : -INFINITY;
        int order[3];
        for (int a = 0; a < 3; a++) {
            int r = 0;
            for (int j = 0; j < 3; j++)
                if (m[j] > m[a] || (m[j] == m[a] && j < a)) r++;
            order[r] = a;
        }
        float x1[3], y1[3], x2[3], y2[3], ar[3];
        for (int i = 0; i < 3; i++) {
            int a = order[i];
            x1[i] = bx1[a]; y1[i] = by1[a]; x2[i] = bx2[a]; y2[i] = by2[a];
            ar[i] = (x2[i] - x1[i]) * (y2[i] - y1[i]);
        }
        bool ks[3], sup[3] = {false, false, false};
        for (int i = 0; i < 3; i++) {
            bool valid = !sup[i];
            ks[i] = valid;
            if (valid) {
                for (int j = i + 1; j < 3; j++) {
                    float ix1 = fmaxf(x1[i], x1[j]), iy1 = fmaxf(y1[i], y1[j]);
                    float ix2 = fminf(x2[i], x2[j]), iy2 = fminf(y2[i], y2[j]);
                    float inter = fmaxf(ix2 - ix1, 0.f) * fmaxf(iy2 - iy1, 0.f);
                    float iou = inter / (ar[i] + ar[j] - inter);
                    if (iou > 0.5f) sup[j] = true;
                }
            }
        }
        bool keep[3];
        for (int i = 0; i < 3; i++) keep[order[i]] = ks[i];
        for (int a = 0; a < 3; a++)
            out[264 + b * 3 + a] = (keep[a] && conf[a]) ? 1.f : 0.f;
    }
}

// ---------------------------------------------------------------------------
extern "C" void kernel_launch(void* const* d_in, const int* in_sizes, int n_in,
                              void* d_out, int out_size)
{
    const float* x    = (const float*)d_in[0];
    const float* rw1  = (const float*)d_in[1];
    const float* rb1  = (const float*)d_in[2];
    const float* rw2  = (const float*)d_in[3];
    const float* rb2  = (const float*)d_in[4];
    const float* iw1  = (const float*)d_in[5];
    const float* ib1  = (const float*)d_in[6];
    const float* iw2  = (const float*)d_in[7];
    const float* ib2  = (const float*)d_in[8];
    const float* fw   = (const float*)d_in[9];
    const float* fb   = (const float*)d_in[10];
    const float* dw   = (const float*)d_in[11];
    const float* db   = (const float*)d_in[12];
    float* out = (float*)d_out;

    k_s1  <<<dim3(8, 32, 32), 256>>>(x, rw1, rb1, iw1, ib1);
    k_s2  <<<dim3(64, 4, 16), 256>>>(rw2, rb2, iw2, ib2);
    k_fuse<<<dim3(16, 8, 8),  256>>>(fw, fb);
    k_det <<<1, 256>>>(dw, db, out);
}

// round 8
// speedup vs baseline: 1.7136x; 1.7136x over previous
#include <cuda_runtime.h>
#include <math.h>

// ---------------------------------------------------------------------------
// MultiStreamCNN: two conv-pool streams on same input, concat, fuse conv,
// global mean, 1x1 det head, sigmoid + 3-box NMS.
// Heavy convs: packed fp32x2 FMA (fma.rn.f32x2), odd-stride smem patches.
// R8: cp.async triple-buffered patch pipeline in k_s2/k_fuse (zero fill
// exposure, 1 sync/iter instead of 2).
// ---------------------------------------------------------------------------

typedef unsigned long long u64;

__device__ __forceinline__ u64 pk2(float lo, float hi) {
    u64 r; asm("mov.b64 %0,{%1,%2};" : "=l"(r) : "f"(lo), "f"(hi)); return r;
}
__device__ __forceinline__ u64 pkdup(float v) {
    u64 r; asm("mov.b64 %0,{%1,%1};" : "=l"(r) : "f"(v)); return r;
}
__device__ __forceinline__ void upk(u64 v, float& lo, float& hi) {
    asm("mov.b64 {%0,%1},%2;" : "=f"(lo), "=f"(hi) : "l"(v));
}
__device__ __forceinline__ void fma2(u64& d, u64 a, u64 b) {
    asm("fma.rn.f32x2 %0,%1,%2,%0;" : "+l"(d) : "l"(a), "l"(b));
}

// Scratch (device globals: no runtime allocation allowed)
__device__ float g_s1[16u * 32u * 256u * 256u];   // [stream*8+b][32][256][256]
__device__ float g_s2[8u * 128u * 128u * 128u];   // [b][128][128][128]
__device__ float g_part[8 * 128 * 16];            // fuse partial sums

#define PSTR 35  // patch row stride (odd -> conflict-free stride-2 access)

// Async fill of one 34x34 plane patch (with halo, zero-filled OOB) into the
// smem buffer at shared-address dstb. Always commits exactly one group.
// bound = plane width/height (256 for s2 input, 128 for fuse input).
__device__ __forceinline__ void cp_fill(const float* __restrict__ pl, int present,
                                        int tid, int y0, int x0,
                                        unsigned bound, unsigned dstb)
{
    if (present) {
#pragma unroll
        for (int j = 0; j < 5; j++) {
            int i = tid + j * 256;
            if (i < 34 * 34) {
                int r = i / 34, c = i - r * 34;
                int y = y0 + r, x = x0 + c;
                bool inb = ((unsigned)y < bound) && ((unsigned)x < bound);
                const float* src = pl + (inb ? (y * (int)bound + x) : 0);
                int sz = inb ? 4 : 0;
                unsigned dst = dstb + (unsigned)(r * PSTR + c) * 4u;
                asm volatile("cp.async.ca.shared.global [%0], [%1], 4, %2;"
                             :: "r"(dst), "l"(src), "r"(sz) : "memory");
            }
        }
    }
    asm volatile("cp.async.commit_group;" ::: "memory");
}
__device__ __forceinline__ void cp_wait1() {
    asm volatile("cp.async.wait_group 1;" ::: "memory");
}

// ---------------------------------------------------------------------------
// Kernel A: conv1(3x3, 3->32) + relu + maxpool2 for BOTH streams. (unchanged)
// ---------------------------------------------------------------------------
__global__ __launch_bounds__(256, 2) void k_s1(
    const float* __restrict__ x,
    const float* __restrict__ rw, const float* __restrict__ rb,
    const float* __restrict__ iw, const float* __restrict__ ib)
{
    __shared__ float patch[3][18][67];
    __shared__ __align__(16) u64 wp[27][8];
    __shared__ u64 bp[8];

    const int tid = threadIdx.x;
    const int bx = blockIdx.x;
    const int by = blockIdx.y;
    const int bz = blockIdx.z;            // b*4+ocg
    const int b = bz >> 2, ocg = bz & 3;
    const int stream = ocg >> 1;
    const int obase = (ocg & 1) * 16;
    const float* w  = stream ? iw : rw;
    const float* bb = stream ? ib : rb;

    for (int i = tid; i < 27 * 8; i += 256) {
        int pr = i & 7, k = i >> 3;
        int ic = k / 9, kk = k % 9, ky = kk / 3, kx = kk % 3;
        int o0 = obase + 2 * pr;
        wp[k][pr] = pk2(w[((o0 * 3 + ic) * 3 + ky) * 3 + kx],
                        w[(((o0 + 1) * 3 + ic) * 3 + ky) * 3 + kx]);
    }
    if (tid < 8) bp[tid] = pk2(bb[obase + 2 * tid], bb[obase + 2 * tid + 1]);

    const int y0 = 16 * by - 1, x0 = 64 * bx - 1;
    const float* xin = x + (size_t)b * 3 * 512 * 512;
    for (int i = tid; i < 3 * 18 * 66; i += 256) {
        int ic = i / (18 * 66); int r = (i / 66) % 18; int c = i % 66;
        int y = y0 + r, xg = x0 + c;
        float v = 0.f;
        if ((unsigned)y < 512u && (unsigned)xg < 512u)
            v = xin[((size_t)ic * 512 + y) * 512 + xg];
        patch[ic][r][c] = v;
    }
    __syncthreads();

    const int tx = tid & 31, ty = tid >> 5;
    u64 acc[4][8];
#pragma unroll
    for (int p = 0; p < 4; p++)
#pragma unroll
        for (int pr = 0; pr < 8; pr++) acc[p][pr] = bp[pr];

#pragma unroll
    for (int ic = 0; ic < 3; ic++)
#pragma unroll
        for (int ky = 0; ky < 3; ky++)
#pragma unroll
            for (int kx = 0; kx < 3; kx++) {
                const int k = ic * 9 + ky * 3 + kx;
                u64 w8[8];
#pragma unroll
                for (int q = 0; q < 4; q++) {
                    ulonglong2 v2 = *(const ulonglong2*)&wp[k][2 * q];
                    w8[2 * q] = v2.x; w8[2 * q + 1] = v2.y;
                }
#pragma unroll
                for (int dy = 0; dy < 2; dy++)
#pragma unroll
                    for (int dx = 0; dx < 2; dx++) {
                        u64 a = pkdup(patch[ic][2 * ty + dy + ky][2 * tx + dx + kx]);
                        const int p = dy * 2 + dx;
#pragma unroll
                        for (int pr = 0; pr < 8; pr++) fma2(acc[p][pr], a, w8[pr]);
                    }
            }

    const int py = 8 * by + ty, px = 32 * bx + tx;
    float* outp = g_s1 + ((((size_t)(stream * 8 + b)) * 32 + obase) * 256 + py) * 256 + px;
#pragma unroll
    for (int pr = 0; pr < 8; pr++) {
        float l0, h0, l1, h1, l2, h2, l3, h3;
        upk(acc[0][pr], l0, h0); upk(acc[1][pr], l1, h1);
        upk(acc[2][pr], l2, h2); upk(acc[3][pr], l3, h3);
        float vlo = fmaxf(fmaxf(fmaxf(l0, l1), fmaxf(l2, l3)), 0.f);
        float vhi = fmaxf(fmaxf(fmaxf(h0, h1), fmaxf(h2, h3)), 0.f);
        outp[(size_t)(2 * pr) * 65536] = vlo;
        outp[(size_t)(2 * pr + 1) * 65536] = vhi;
    }
}

// ---------------------------------------------------------------------------
// Kernel B: conv2(3x3, 32->64) + relu + maxpool2 per stream.
// cp.async triple-buffered input pipeline over the 32 input channels.
// ---------------------------------------------------------------------------
__global__ __launch_bounds__(256, 2) void k_s2(
    const float* __restrict__ rw, const float* __restrict__ rb,
    const float* __restrict__ iw, const float* __restrict__ ib)
{
    __shared__ float patch[3][34 * PSTR];
    __shared__ __align__(16) u64 wp[288][8];
    __shared__ u64 bp[8];

    const int tid = threadIdx.x;
    const int t = blockIdx.x;     // 0..63
    const int tX = t & 7, tY = t >> 3;
    const int ocg = blockIdx.y;   // 0..3
    const int bz = blockIdx.z;    // stream*8+b
    const int s = bz >> 3, b = bz & 7;
    const float* w  = s ? iw : rw;
    const float* bb = s ? ib : rb;
    const int obase = ocg * 16;

    for (int i = tid; i < 288 * 8; i += 256) {
        int pr = i & 7, k = i >> 3;
        int ic = k / 9, kk = k % 9, ky = kk / 3, kx = kk % 3;
        int o0 = obase + 2 * pr;
        wp[k][pr] = pk2(w[((o0 * 32 + ic) * 3 + ky) * 3 + kx],
                        w[(((o0 + 1) * 32 + ic) * 3 + ky) * 3 + kx]);
    }
    if (tid < 8) bp[tid] = pk2(bb[obase + 2 * tid], bb[obase + 2 * tid + 1]);

    const int y0 = 32 * tY - 1, x0 = 32 * tX - 1;
    const float* plane = g_s1 + (size_t)bz * 32 * 65536;
    unsigned pb[3];
#pragma unroll
    for (int q = 0; q < 3; q++)
        pb[q] = (unsigned)__cvta_generic_to_shared(&patch[q][0]);

    // Pipeline prologue: planes 0 and 1 in flight.
    cp_fill(plane, 1, tid, y0, x0, 256u, pb[0]);
    cp_fill(plane + 65536, 1, tid, y0, x0, 256u, pb[1]);
    __syncthreads();  // wp/bp visible

    const int ttx = tid & 15, tty = tid >> 4;
    u64 acc[4][8];
#pragma unroll
    for (int p = 0; p < 4; p++)
#pragma unroll
        for (int pr = 0; pr < 8; pr++) acc[p][pr] = bp[pr];

    int s0 = 0, s1 = 1, s2 = 2;  // reading / pending / issuing slots
    for (int ic = 0; ic < 32; ic++) {
        cp_wait1();          // group(ic) complete (group(ic+1) may be pending)
        __syncthreads();     // data visible; slot s2's previous readers done
        cp_fill(plane + (size_t)(ic + 2) * 65536, (ic + 2) < 32,
                tid, y0, x0, 256u, pb[s2]);
        const float* pbuf = patch[s0];
#pragma unroll
        for (int kk = 0; kk < 9; kk++) {
            const int ky = kk / 3, kx = kk % 3;
            u64 w8[8];
#pragma unroll
            for (int q = 0; q < 4; q++) {
                ulonglong2 v2 = *(const ulonglong2*)&wp[ic * 9 + kk][2 * q];
                w8[2 * q] = v2.x; w8[2 * q + 1] = v2.y;
            }
#pragma unroll
            for (int dy = 0; dy < 2; dy++)
#pragma unroll
                for (int dx = 0; dx < 2; dx++) {
                    u64 a = pkdup(pbuf[(2 * tty + dy + ky) * PSTR + 2 * ttx + dx + kx]);
                    const int p = dy * 2 + dx;
#pragma unroll
                    for (int pr = 0; pr < 8; pr++) fma2(acc[p][pr], a, w8[pr]);
                }
        }
        int tmp = s0; s0 = s1; s1 = s2; s2 = tmp;
    }

    const int py = 16 * tY + tty, px = 16 * tX + ttx;
    float* outp = g_s2 + ((size_t)(b * 128 + s * 64 + obase) * 128 + py) * 128 + px;
#pragma unroll
    for (int pr = 0; pr < 8; pr++) {
        float l0, h0, l1, h1, l2, h2, l3, h3;
        upk(acc[0][pr], l0, h0); upk(acc[1][pr], l1, h1);
        upk(acc[2][pr], l2, h2); upk(acc[3][pr], l3, h3);
        float vlo = fmaxf(fmaxf(fmaxf(l0, l1), fmaxf(l2, l3)), 0.f);
        float vhi = fmaxf(fmaxf(fmaxf(h0, h1), fmaxf(h2, h3)), 0.f);
        outp[(size_t)(2 * pr) * 16384] = vlo;
        outp[(size_t)(2 * pr + 1) * 16384] = vhi;
    }
}

// ---------------------------------------------------------------------------
// Kernel C: fuse conv(3x3, 128->128) + relu -> per-tile channel sums.
// cp.async triple-buffered pipeline over 128 input channels; weights staged
// in 4 chunks of 32 ic.
// ---------------------------------------------------------------------------
__global__ __launch_bounds__(256, 2) void k_fuse(
    const float* __restrict__ fw, const float* __restrict__ fb)
{
    __shared__ float patch[3][34 * PSTR];
    __shared__ __align__(16) u64 wp[288][8];
    __shared__ u64 bp[8];
    __shared__ float red[8][16];

    const int tid = threadIdx.x;
    const int t = blockIdx.x;   // 0..15
    const int tX = t & 3, tY = t >> 2;
    const int ocg = blockIdx.y; // 0..7
    const int b = blockIdx.z;
    const int obase = ocg * 16;

    // Stage weights for chunk 0 + bias.
    for (int i = tid; i < 288 * 8; i += 256) {
        int pr = i & 7, k = i >> 3;
        int icc = k / 9, kk = k % 9, ky = kk / 3, kx = kk % 3;
        int o0 = obase + 2 * pr;
        wp[k][pr] = pk2(fw[((o0 * 128 + icc) * 3 + ky) * 3 + kx],
                        fw[(((o0 + 1) * 128 + icc) * 3 + ky) * 3 + kx]);
    }
    if (tid < 8) bp[tid] = pk2(fb[obase + 2 * tid], fb[obase + 2 * tid + 1]);

    const int y0 = 32 * tY - 1, x0 = 32 * tX - 1;
    const float* base = g_s2 + (size_t)b * 128 * 16384;
    unsigned pb[3];
#pragma unroll
    for (int q = 0; q < 3; q++)
        pb[q] = (unsigned)__cvta_generic_to_shared(&patch[q][0]);

    cp_fill(base, 1, tid, y0, x0, 128u, pb[0]);
    cp_fill(base + 16384, 1, tid, y0, x0, 128u, pb[1]);
    __syncthreads();  // wp(chunk0)/bp visible

    const int ttx = tid & 15, tty = tid >> 4;
    u64 acc[4][8];
#pragma unroll
    for (int p = 0; p < 4; p++)
#pragma unroll
        for (int pr = 0; pr < 8; pr++) acc[p][pr] = bp[pr];

    int s0 = 0, s1 = 1, s2 = 2;
    for (int ic = 0; ic < 128; ic++) {
        cp_wait1();
        __syncthreads();
        if (ic && !(ic & 31)) {  // new weight chunk; prev compute done (sync above)
            const int ch = ic >> 5;
            for (int i = tid; i < 288 * 8; i += 256) {
                int pr = i & 7, k = i >> 3;
                int icc = k / 9, kk = k % 9, ky = kk / 3, kx = kk % 3;
                int icg = ch * 32 + icc;
                int o0 = obase + 2 * pr;
                wp[k][pr] = pk2(fw[((o0 * 128 + icg) * 3 + ky) * 3 + kx],
                                fw[(((o0 + 1) * 128 + icg) * 3 + ky) * 3 + kx]);
            }
            __syncthreads();  // wp visible
        }
        cp_fill(base + (size_t)(ic + 2) * 16384, (ic + 2) < 128,
                tid, y0, x0, 128u, pb[s2]);
        const int icc = ic & 31;
        const float* pbuf = patch[s0];
#pragma unroll
        for (int kk = 0; kk < 9; kk++) {
            const int ky = kk / 3, kx = kk % 3;
            u64 w8[8];
#pragma unroll
            for (int q = 0; q < 4; q++) {
                ulonglong2 v2 = *(const ulonglong2*)&wp[icc * 9 + kk][2 * q];
                w8[2 * q] = v2.x; w8[2 * q + 1] = v2.y;
            }
#pragma unroll
            for (int dy = 0; dy < 2; dy++)
#pragma unroll
                for (int dx = 0; dx < 2; dx++) {
                    u64 a = pkdup(pbuf[(2 * tty + dy + ky) * PSTR + 2 * ttx + dx + kx]);
                    const int p = dy * 2 + dx;
#pragma unroll
                    for (int pr = 0; pr < 8; pr++) fma2(acc[p][pr], a, w8[pr]);
                }
        }
        int tmp = s0; s0 = s1; s1 = s2; s2 = tmp;
    }

    // relu + per-thread sum of the 4 pixels, per output channel
    float sum[16];
#pragma unroll
    for (int pr = 0; pr < 8; pr++) {
        float l0, h0, l1, h1, l2, h2, l3, h3;
        upk(acc[0][pr], l0, h0); upk(acc[1][pr], l1, h1);
        upk(acc[2][pr], l2, h2); upk(acc[3][pr], l3, h3);
        sum[2 * pr]     = fmaxf(l0, 0.f) + fmaxf(l1, 0.f) + fmaxf(l2, 0.f) + fmaxf(l3, 0.f);
        sum[2 * pr + 1] = fmaxf(h0, 0.f) + fmaxf(h1, 0.f) + fmaxf(h2, 0.f) + fmaxf(h3, 0.f);
    }
    const int wid = tid >> 5, lid = tid & 31;
#pragma unroll
    for (int o = 0; o < 16; o++) {
        float v = sum[o];
        v += __shfl_down_sync(0xffffffffu, v, 16);
        v += __shfl_down_sync(0xffffffffu, v, 8);
        v += __shfl_down_sync(0xffffffffu, v, 4);
        v += __shfl_down_sync(0xffffffffu, v, 2);
        v += __shfl_down_sync(0xffffffffu, v, 1);
        if (lid == 0) red[wid][o] = v;
    }
    __syncthreads();
    if (tid < 16) {
        float sacc = 0.f;
        for (int w8 = 0; w8 < 8; w8++) sacc += red[w8][tid];
        g_part[(b * 128 + obase + tid) * 16 + t] = sacc;
    }
}

// ---------------------------------------------------------------------------
// Kernel D: finish. (unchanged)
// ---------------------------------------------------------------------------
__global__ void k_det(const float* __restrict__ dw, const float* __restrict__ db,
                      float* __restrict__ out)
{
    __shared__ float favg[1024];
    __shared__ float pp[144];
    const int tid = threadIdx.x;  // 256

    for (int i = tid; i < 1024; i += 256) {
        float s = 0.f;
        const float* pr = g_part + i * 16;
#pragma unroll
        for (int t = 0; t < 16; t++) s += pr[t];
        favg[i] = s * (1.f / 16384.f);
    }
    __syncthreads();

    if (tid < 144) {
        const int b = tid / 18, ch = tid % 18;
        float s = db[ch];
        const float* w = dw + ch * 128;
        const float* f = favg + b * 128;
#pragma unroll 8
        for (int c = 0; c < 128; c++) s = fmaf(w[c], f[c], s);
        pp[tid] = s;
        out[tid] = s;
    }
    __syncthreads();

    if (tid < 8) {
        const int b = tid;
        const float* P = pp + b * 18;
        float sc[3]; bool conf[3];
        float bx1[3], by1[3], bx2[3], by2[3];
        for (int a = 0; a < 3; a++) {
            bx1[a] = P[a * 6 + 0]; by1[a] = P[a * 6 + 1];
            bx2[a] = P[a * 6 + 2]; by2[a] = P[a * 6 + 3];
            sc[a] = 1.f / (1.f + expf(-P[a * 6 + 4]));
            conf[a] = sc[a] > 0.5f;
            out[144 + b * 12 + a * 4 + 0] = bx1[a];
            out[144 + b * 12 + a * 4 + 1] = by1[a];
            out[144 + b * 12 + a * 4 + 2] = bx2[a];
            out[144 + b * 12 + a * 4 + 3] = by2[a];
            out[240 + b * 3 + a] = sc[a];
        }
        float m[3];
        for (int a = 0; a < 3; a++) m[a] = conf[a] ? sc[a] : -INFINITY;
        int order[3];
        for (int a = 0; a < 3; a++) {
            int r = 0;
            for (int j = 0; j < 3; j++)
                if (m[j] > m[a] || (m[j] == m[a] && j < a)) r++;
            order[r] = a;
        }
        float x1[3], y1[3], x2[3], y2[3], ar[3];
        for (int i = 0; i < 3; i++) {
            int a = order[i];
            x1[i] = bx1[a]; y1[i] = by1[a]; x2[i] = bx2[a]; y2[i] = by2[a];
            ar[i] = (x2[i] - x1[i]) * (y2[i] - y1[i]);
        }
        bool ks[3], sup[3] = {false, false, false};
        for (int i = 0; i < 3; i++) {
            bool valid = !sup[i];
            ks[i] = valid;
            if (valid) {
                for (int j = i + 1; j < 3; j++) {
                    float ix1 = fmaxf(x1[i], x1[j]), iy1 = fmaxf(y1[i], y1[j]);
                    float ix2 = fminf(x2[i], x2[j]), iy2 = fminf(y2[i], y2[j]);
                    float inter = fmaxf(ix2 - ix1, 0.f) * fmaxf(iy2 - iy1, 0.f);
                    float iou = inter / (ar[i] + ar[j] - inter);
                    if (iou > 0.5f) sup[j] = true;
                }
            }
        }
        bool keep[3];
        for (int i = 0; i < 3; i++) keep[order[i]] = ks[i];
        for (int a = 0; a < 3; a++)
            out[264 + b * 3 + a] = (keep[a] && conf[a]) ? 1.f : 0.f;
    }
}

// ---------------------------------------------------------------------------
extern "C" void kernel_launch(void* const* d_in, const int* in_sizes, int n_in,
                              void* d_out, int out_size)
{
    const float* x    = (const float*)d_in[0];
    const float* rw1  = (const float*)d_in[1];
    const float* rb1  = (const float*)d_in[2];
    const float* rw2  = (const float*)d_in[3];
    const float* rb2  = (const float*)d_in[4];
    const float* iw1  = (const float*)d_in[5];
    const float* ib1  = (const float*)d_in[6];
    const float* iw2  = (const float*)d_in[7];
    const float* ib2  = (const float*)d_in[8];
    const float* fw   = (const float*)d_in[9];
    const float* fb   = (const float*)d_in[10];
    const float* dw   = (const float*)d_in[11];
    const float* db   = (const float*)d_in[12];
    float* out = (float*)d_out;

    k_s1  <<<dim3(8, 32, 32), 256>>>(x, rw1, rb1, iw1, ib1);
    k_s2  <<<dim3(64, 4, 16), 256>>>(rw2, rb2, iw2, ib2);
    k_fuse<<<dim3(16, 8, 8),  256>>>(fw, fb);
    k_det <<<1, 256>>>(dw, db, out);
}